// round 5
// baseline (speedup 1.0000x reference)
#include <cuda_runtime.h>
#include <math.h>

#define BATCH  4
#define SEQ    2048
#define EMBED  256
#define HIDDEN 512
#define ROWS   (BATCH * SEQ)   // 8192

// -------- scratch (allocation-free: __device__ globals) --------
__device__ float g_act[ROWS * HIDDEN];                    // 16 MB
__device__ float g_q[ROWS * HIDDEN];                      // 16 MB
__device__ float g_k[ROWS * HIDDEN];                      // 16 MB
__device__ float g_v[ROWS * HIDDEN];                      // 16 MB
__device__ float g_scores[(size_t)BATCH * SEQ * SEQ];     // 64 MB

// ============================================================
// Kernel 1: act = gelu( emb_table[tok] @ W1 + b1 )
// M=8192, K=256, N=512. 64x64 tile, 4x4 micro, BK=16.
// ============================================================
__global__ void embed_mlp_kernel(const int* __restrict__ tok,
                                 const float* __restrict__ emb,
                                 const float* __restrict__ W1,
                                 const float* __restrict__ b1)
{
    __shared__ float As[64][17];
    __shared__ float Bs[16][64];

    const int tile_n = blockIdx.x * 64;
    const int tile_m = blockIdx.y * 64;
    const int t  = threadIdx.x;        // 0..255
    const int tx = t & 15;
    const int ty = t >> 4;

    float acc[4][4] = {};

    for (int k0 = 0; k0 < EMBED; k0 += 16) {
        #pragma unroll
        for (int i = 0; i < 4; i++) {
            int idx = t + i * 256;
            int r = idx >> 4, c = idx & 15;
            int token = tok[tile_m + r];
            As[r][c] = emb[(size_t)token * EMBED + k0 + c];
        }
        #pragma unroll
        for (int i = 0; i < 4; i++) {
            int idx = t + i * 256;
            int r = idx >> 6, c = idx & 63;
            Bs[r][c] = W1[(k0 + r) * HIDDEN + tile_n + c];
        }
        __syncthreads();
        #pragma unroll
        for (int kk = 0; kk < 16; kk++) {
            float a[4], b[4];
            #pragma unroll
            for (int i = 0; i < 4; i++) a[i] = As[ty * 4 + i][kk];
            #pragma unroll
            for (int j = 0; j < 4; j++) b[j] = Bs[kk][tx * 4 + j];
            #pragma unroll
            for (int i = 0; i < 4; i++)
                #pragma unroll
                for (int j = 0; j < 4; j++)
                    acc[i][j] = fmaf(a[i], b[j], acc[i][j]);
        }
        __syncthreads();
    }

    #pragma unroll
    for (int i = 0; i < 4; i++) {
        int row = tile_m + ty * 4 + i;
        #pragma unroll
        for (int j = 0; j < 4; j++) {
            int col = tile_n + tx * 4 + j;
            float x = acc[i][j] + b1[col];
            // exact GELU: 0.5*x*(1+erf(x/sqrt(2)))
            float g = 0.5f * x * (1.0f + erff(x * 0.7071067811865475f));
            g_act[(size_t)row * HIDDEN + col] = g;
        }
    }
}

// ============================================================
// Kernel 2: q/k/v = act @ W{q,k,v} + b{q,k,v}   (blockIdx.z selects)
// M=8192, K=512, N=512.
// ============================================================
__global__ void qkv_kernel(const float* __restrict__ Wq, const float* __restrict__ bq,
                           const float* __restrict__ Wk, const float* __restrict__ bk,
                           const float* __restrict__ Wv, const float* __restrict__ bv)
{
    __shared__ float As[64][17];
    __shared__ float Bs[16][64];

    const float* W; const float* bias; float* out;
    if      (blockIdx.z == 0) { W = Wq; bias = bq; out = g_q; }
    else if (blockIdx.z == 1) { W = Wk; bias = bk; out = g_k; }
    else                      { W = Wv; bias = bv; out = g_v; }

    const int tile_n = blockIdx.x * 64;
    const int tile_m = blockIdx.y * 64;
    const int t  = threadIdx.x;
    const int tx = t & 15;
    const int ty = t >> 4;

    float acc[4][4] = {};

    for (int k0 = 0; k0 < HIDDEN; k0 += 16) {
        #pragma unroll
        for (int i = 0; i < 4; i++) {
            int idx = t + i * 256;
            int r = idx >> 4, c = idx & 15;
            As[r][c] = g_act[(size_t)(tile_m + r) * HIDDEN + k0 + c];
        }
        #pragma unroll
        for (int i = 0; i < 4; i++) {
            int idx = t + i * 256;
            int r = idx >> 6, c = idx & 63;
            Bs[r][c] = W[(k0 + r) * HIDDEN + tile_n + c];
        }
        __syncthreads();
        #pragma unroll
        for (int kk = 0; kk < 16; kk++) {
            float a[4], b[4];
            #pragma unroll
            for (int i = 0; i < 4; i++) a[i] = As[ty * 4 + i][kk];
            #pragma unroll
            for (int j = 0; j < 4; j++) b[j] = Bs[kk][tx * 4 + j];
            #pragma unroll
            for (int i = 0; i < 4; i++)
                #pragma unroll
                for (int j = 0; j < 4; j++)
                    acc[i][j] = fmaf(a[i], b[j], acc[i][j]);
        }
        __syncthreads();
    }

    #pragma unroll
    for (int i = 0; i < 4; i++) {
        int row = tile_m + ty * 4 + i;
        #pragma unroll
        for (int j = 0; j < 4; j++) {
            int col = tile_n + tx * 4 + j;
            out[(size_t)row * HIDDEN + col] = acc[i][j] + bias[col];
        }
    }
}

// ============================================================
// Kernel 3: scores[b,s,t] = dot(q[b,s,:], k[b,t,:]) / sqrt(512)
// Per batch z: M=2048 (s), N=2048 (t), K=512 (h). Both operands K-major.
// ============================================================
__global__ void scores_kernel()
{
    __shared__ float Qs[64][17];
    __shared__ float Ks[64][17];

    const int z = blockIdx.z;
    const float* Q = g_q + (size_t)z * SEQ * HIDDEN;
    const float* K = g_k + (size_t)z * SEQ * HIDDEN;
    float* C = g_scores + (size_t)z * SEQ * SEQ;

    const int tile_n = blockIdx.x * 64;   // t
    const int tile_m = blockIdx.y * 64;   // s
    const int t  = threadIdx.x;
    const int tx = t & 15;
    const int ty = t >> 4;

    float acc[4][4] = {};

    for (int k0 = 0; k0 < HIDDEN; k0 += 16) {
        #pragma unroll
        for (int i = 0; i < 4; i++) {
            int idx = t + i * 256;
            int r = idx >> 4, c = idx & 15;
            Qs[r][c] = Q[(size_t)(tile_m + r) * HIDDEN + k0 + c];
            Ks[r][c] = K[(size_t)(tile_n + r) * HIDDEN + k0 + c];
        }
        __syncthreads();
        #pragma unroll
        for (int kk = 0; kk < 16; kk++) {
            float a[4], b[4];
            #pragma unroll
            for (int i = 0; i < 4; i++) a[i] = Qs[ty * 4 + i][kk];
            #pragma unroll
            for (int j = 0; j < 4; j++) b[j] = Ks[tx * 4 + j][kk];
            #pragma unroll
            for (int i = 0; i < 4; i++)
                #pragma unroll
                for (int j = 0; j < 4; j++)
                    acc[i][j] = fmaf(a[i], b[j], acc[i][j]);
        }
        __syncthreads();
    }

    const float scale = 0.04419417382415922f;   // 1/sqrt(512)
    #pragma unroll
    for (int i = 0; i < 4; i++) {
        int row = tile_m + ty * 4 + i;
        #pragma unroll
        for (int j = 0; j < 4; j++) {
            int col = tile_n + tx * 4 + j;
            C[(size_t)row * SEQ + col] = acc[i][j] * scale;
        }
    }
}

// ============================================================
// Kernel 4: row softmax over g_scores (8192 rows x 2048)
// ============================================================
__global__ void softmax_kernel()
{
    const int row = blockIdx.x;
    float* p = g_scores + (size_t)row * SEQ;
    const int t = threadIdx.x;       // 256 threads, 8 elems each
    __shared__ float red[16];

    float v[8];
    float lmax = -1e30f;
    #pragma unroll
    for (int i = 0; i < 8; i++) {
        v[i] = p[t + i * 256];
        lmax = fmaxf(lmax, v[i]);
    }
    #pragma unroll
    for (int o = 16; o; o >>= 1)
        lmax = fmaxf(lmax, __shfl_xor_sync(0xffffffffu, lmax, o));
    if ((t & 31) == 0) red[t >> 5] = lmax;
    __syncthreads();
    float rmax = red[0];
    #pragma unroll
    for (int i = 1; i < 8; i++) rmax = fmaxf(rmax, red[i]);

    float lsum = 0.0f;
    #pragma unroll
    for (int i = 0; i < 8; i++) {
        v[i] = __expf(v[i] - rmax);
        lsum += v[i];
    }
    #pragma unroll
    for (int o = 16; o; o >>= 1)
        lsum += __shfl_xor_sync(0xffffffffu, lsum, o);
    if ((t & 31) == 0) red[8 + (t >> 5)] = lsum;
    __syncthreads();
    float total = 0.0f;
    #pragma unroll
    for (int i = 0; i < 8; i++) total += red[8 + i];

    float inv = 1.0f / total;
    #pragma unroll
    for (int i = 0; i < 8; i++)
        p[t + i * 256] = v[i] * inv;
}

// ============================================================
// Kernel 5: out[b,s,:] = attn[b,s,:] @ v[b,:,:]
// Per batch z: M=2048, N=512, K=2048.
// ============================================================
__global__ void out_kernel(float* __restrict__ out)
{
    __shared__ float As[64][17];
    __shared__ float Bs[16][64];

    const int z = blockIdx.z;
    const float* A = g_scores + (size_t)z * SEQ * SEQ;
    const float* V = g_v + (size_t)z * SEQ * HIDDEN;
    float* C = out + (size_t)z * SEQ * HIDDEN;

    const int tile_n = blockIdx.x * 64;
    const int tile_m = blockIdx.y * 64;
    const int t  = threadIdx.x;
    const int tx = t & 15;
    const int ty = t >> 4;

    float acc[4][4] = {};

    for (int k0 = 0; k0 < SEQ; k0 += 16) {
        #pragma unroll
        for (int i = 0; i < 4; i++) {
            int idx = t + i * 256;
            int r = idx >> 4, c = idx & 15;
            As[r][c] = A[(size_t)(tile_m + r) * SEQ + k0 + c];
        }
        #pragma unroll
        for (int i = 0; i < 4; i++) {
            int idx = t + i * 256;
            int r = idx >> 6, c = idx & 63;
            Bs[r][c] = V[(size_t)(k0 + r) * HIDDEN + tile_n + c];
        }
        __syncthreads();
        #pragma unroll
        for (int kk = 0; kk < 16; kk++) {
            float a[4], b[4];
            #pragma unroll
            for (int i = 0; i < 4; i++) a[i] = As[ty * 4 + i][kk];
            #pragma unroll
            for (int j = 0; j < 4; j++) b[j] = Bs[kk][tx * 4 + j];
            #pragma unroll
            for (int i = 0; i < 4; i++)
                #pragma unroll
                for (int j = 0; j < 4; j++)
                    acc[i][j] = fmaf(a[i], b[j], acc[i][j]);
        }
        __syncthreads();
    }

    #pragma unroll
    for (int i = 0; i < 4; i++) {
        int row = tile_m + ty * 4 + i;
        #pragma unroll
        for (int j = 0; j < 4; j++) {
            int col = tile_n + tx * 4 + j;
            C[(size_t)row * HIDDEN + col] = acc[i][j];
        }
    }
}

// ============================================================
// launch
// ============================================================
extern "C" void kernel_launch(void* const* d_in, const int* in_sizes, int n_in,
                              void* d_out, int out_size)
{
    const int*   tok = (const int*)  d_in[0];
    const float* emb = (const float*)d_in[1];
    const float* W1  = (const float*)d_in[2];
    const float* b1  = (const float*)d_in[3];
    const float* Wq  = (const float*)d_in[4];
    const float* bq  = (const float*)d_in[5];
    const float* Wk  = (const float*)d_in[6];
    const float* bk  = (const float*)d_in[7];
    const float* Wv  = (const float*)d_in[8];
    const float* bv  = (const float*)d_in[9];
    float* out = (float*)d_out;

    dim3 blk(256);
    embed_mlp_kernel<<<dim3(HIDDEN / 64, ROWS / 64), blk>>>(tok, emb, W1, b1);
    qkv_kernel<<<dim3(HIDDEN / 64, ROWS / 64, 3), blk>>>(Wq, bq, Wk, bk, Wv, bv);
    scores_kernel<<<dim3(SEQ / 64, SEQ / 64, BATCH), blk>>>();
    softmax_kernel<<<dim3(ROWS), blk>>>();
    out_kernel<<<dim3(HIDDEN / 64, SEQ / 64, BATCH), blk>>>(out);
}

// round 6
// speedup vs baseline: 1.0000x; 1.0000x over previous
#include <cuda_runtime.h>
#include <math.h>

#define BATCH  4
#define SEQ    2048
#define EMBED  256
#define HIDDEN 512
#define ROWS   (BATCH * SEQ)   // 8192

// -------- scratch (allocation-free: __device__ globals) --------
__device__ float g_act[ROWS * HIDDEN];                    // 16 MB
__device__ float g_q[ROWS * HIDDEN];                      // 16 MB
__device__ float g_k[ROWS * HIDDEN];                      // 16 MB
__device__ float g_v[ROWS * HIDDEN];                      // 16 MB
__device__ float g_scores[(size_t)BATCH * SEQ * SEQ];     // 64 MB

// ============================================================
// Kernel 1: act = gelu( emb_table[tok] @ W1 + b1 )
// M=8192, K=256, N=512. 64x64 tile, 4x4 micro, BK=16.
// ============================================================
__global__ void embed_mlp_kernel(const int* __restrict__ tok,
                                 const float* __restrict__ emb,
                                 const float* __restrict__ W1,
                                 const float* __restrict__ b1)
{
    __shared__ float As[64][17];
    __shared__ float Bs[16][64];

    const int tile_n = blockIdx.x * 64;
    const int tile_m = blockIdx.y * 64;
    const int t  = threadIdx.x;        // 0..255
    const int tx = t & 15;
    const int ty = t >> 4;

    float acc[4][4] = {};

    for (int k0 = 0; k0 < EMBED; k0 += 16) {
        #pragma unroll
        for (int i = 0; i < 4; i++) {
            int idx = t + i * 256;
            int r = idx >> 4, c = idx & 15;
            int token = tok[tile_m + r];
            As[r][c] = emb[(size_t)token * EMBED + k0 + c];
        }
        #pragma unroll
        for (int i = 0; i < 4; i++) {
            int idx = t + i * 256;
            int r = idx >> 6, c = idx & 63;
            Bs[r][c] = W1[(k0 + r) * HIDDEN + tile_n + c];
        }
        __syncthreads();
        #pragma unroll
        for (int kk = 0; kk < 16; kk++) {
            float a[4], b[4];
            #pragma unroll
            for (int i = 0; i < 4; i++) a[i] = As[ty * 4 + i][kk];
            #pragma unroll
            for (int j = 0; j < 4; j++) b[j] = Bs[kk][tx * 4 + j];
            #pragma unroll
            for (int i = 0; i < 4; i++)
                #pragma unroll
                for (int j = 0; j < 4; j++)
                    acc[i][j] = fmaf(a[i], b[j], acc[i][j]);
        }
        __syncthreads();
    }

    #pragma unroll
    for (int i = 0; i < 4; i++) {
        int row = tile_m + ty * 4 + i;
        #pragma unroll
        for (int j = 0; j < 4; j++) {
            int col = tile_n + tx * 4 + j;
            float x = acc[i][j] + b1[col];
            // exact GELU: 0.5*x*(1+erf(x/sqrt(2)))
            float g = 0.5f * x * (1.0f + erff(x * 0.7071067811865475f));
            g_act[(size_t)row * HIDDEN + col] = g;
        }
    }
}

// ============================================================
// Kernel 2: q/k/v = act @ W{q,k,v} + b{q,k,v}   (blockIdx.z selects)
// M=8192, K=512, N=512.
// ============================================================
__global__ void qkv_kernel(const float* __restrict__ Wq, const float* __restrict__ bq,
                           const float* __restrict__ Wk, const float* __restrict__ bk,
                           const float* __restrict__ Wv, const float* __restrict__ bv)
{
    __shared__ float As[64][17];
    __shared__ float Bs[16][64];

    const float* W; const float* bias; float* out;
    if      (blockIdx.z == 0) { W = Wq; bias = bq; out = g_q; }
    else if (blockIdx.z == 1) { W = Wk; bias = bk; out = g_k; }
    else                      { W = Wv; bias = bv; out = g_v; }

    const int tile_n = blockIdx.x * 64;
    const int tile_m = blockIdx.y * 64;
    const int t  = threadIdx.x;
    const int tx = t & 15;
    const int ty = t >> 4;

    float acc[4][4] = {};

    for (int k0 = 0; k0 < HIDDEN; k0 += 16) {
        #pragma unroll
        for (int i = 0; i < 4; i++) {
            int idx = t + i * 256;
            int r = idx >> 4, c = idx & 15;
            As[r][c] = g_act[(size_t)(tile_m + r) * HIDDEN + k0 + c];
        }
        #pragma unroll
        for (int i = 0; i < 4; i++) {
            int idx = t + i * 256;
            int r = idx >> 6, c = idx & 63;
            Bs[r][c] = W[(k0 + r) * HIDDEN + tile_n + c];
        }
        __syncthreads();
        #pragma unroll
        for (int kk = 0; kk < 16; kk++) {
            float a[4], b[4];
            #pragma unroll
            for (int i = 0; i < 4; i++) a[i] = As[ty * 4 + i][kk];
            #pragma unroll
            for (int j = 0; j < 4; j++) b[j] = Bs[kk][tx * 4 + j];
            #pragma unroll
            for (int i = 0; i < 4; i++)
                #pragma unroll
                for (int j = 0; j < 4; j++)
                    acc[i][j] = fmaf(a[i], b[j], acc[i][j]);
        }
        __syncthreads();
    }

    #pragma unroll
    for (int i = 0; i < 4; i++) {
        int row = tile_m + ty * 4 + i;
        #pragma unroll
        for (int j = 0; j < 4; j++) {
            int col = tile_n + tx * 4 + j;
            out[(size_t)row * HIDDEN + col] = acc[i][j] + bias[col];
        }
    }
}

// ============================================================
// Kernel 3: scores[b,s,t] = dot(q[b,s,:], k[b,t,:]) / sqrt(512)
// Per batch z: M=2048 (s), N=2048 (t), K=512 (h). Both operands K-major.
// ============================================================
__global__ void scores_kernel()
{
    __shared__ float Qs[64][17];
    __shared__ float Ks[64][17];

    const int z = blockIdx.z;
    const float* Q = g_q + (size_t)z * SEQ * HIDDEN;
    const float* K = g_k + (size_t)z * SEQ * HIDDEN;
    float* C = g_scores + (size_t)z * SEQ * SEQ;

    const int tile_n = blockIdx.x * 64;   // t
    const int tile_m = blockIdx.y * 64;   // s
    const int t  = threadIdx.x;
    const int tx = t & 15;
    const int ty = t >> 4;

    float acc[4][4] = {};

    for (int k0 = 0; k0 < HIDDEN; k0 += 16) {
        #pragma unroll
        for (int i = 0; i < 4; i++) {
            int idx = t + i * 256;
            int r = idx >> 4, c = idx & 15;
            Qs[r][c] = Q[(size_t)(tile_m + r) * HIDDEN + k0 + c];
            Ks[r][c] = K[(size_t)(tile_n + r) * HIDDEN + k0 + c];
        }
        __syncthreads();
        #pragma unroll
        for (int kk = 0; kk < 16; kk++) {
            float a[4], b[4];
            #pragma unroll
            for (int i = 0; i < 4; i++) a[i] = Qs[ty * 4 + i][kk];
            #pragma unroll
            for (int j = 0; j < 4; j++) b[j] = Ks[tx * 4 + j][kk];
            #pragma unroll
            for (int i = 0; i < 4; i++)
                #pragma unroll
                for (int j = 0; j < 4; j++)
                    acc[i][j] = fmaf(a[i], b[j], acc[i][j]);
        }
        __syncthreads();
    }

    const float scale = 0.04419417382415922f;   // 1/sqrt(512)
    #pragma unroll
    for (int i = 0; i < 4; i++) {
        int row = tile_m + ty * 4 + i;
        #pragma unroll
        for (int j = 0; j < 4; j++) {
            int col = tile_n + tx * 4 + j;
            C[(size_t)row * SEQ + col] = acc[i][j] * scale;
        }
    }
}

// ============================================================
// Kernel 4: row softmax over g_scores (8192 rows x 2048)
// ============================================================
__global__ void softmax_kernel()
{
    const int row = blockIdx.x;
    float* p = g_scores + (size_t)row * SEQ;
    const int t = threadIdx.x;       // 256 threads, 8 elems each
    __shared__ float red[16];

    float v[8];
    float lmax = -1e30f;
    #pragma unroll
    for (int i = 0; i < 8; i++) {
        v[i] = p[t + i * 256];
        lmax = fmaxf(lmax, v[i]);
    }
    #pragma unroll
    for (int o = 16; o; o >>= 1)
        lmax = fmaxf(lmax, __shfl_xor_sync(0xffffffffu, lmax, o));
    if ((t & 31) == 0) red[t >> 5] = lmax;
    __syncthreads();
    float rmax = red[0];
    #pragma unroll
    for (int i = 1; i < 8; i++) rmax = fmaxf(rmax, red[i]);

    float lsum = 0.0f;
    #pragma unroll
    for (int i = 0; i < 8; i++) {
        v[i] = __expf(v[i] - rmax);
        lsum += v[i];
    }
    #pragma unroll
    for (int o = 16; o; o >>= 1)
        lsum += __shfl_xor_sync(0xffffffffu, lsum, o);
    if ((t & 31) == 0) red[8 + (t >> 5)] = lsum;
    __syncthreads();
    float total = 0.0f;
    #pragma unroll
    for (int i = 0; i < 8; i++) total += red[8 + i];

    float inv = 1.0f / total;
    #pragma unroll
    for (int i = 0; i < 8; i++)
        p[t + i * 256] = v[i] * inv;
}

// ============================================================
// Kernel 5: out[b,s,:] = attn[b,s,:] @ v[b,:,:]
// Per batch z: M=2048, N=512, K=2048.
// ============================================================
__global__ void out_kernel(float* __restrict__ out)
{
    __shared__ float As[64][17];
    __shared__ float Bs[16][64];

    const int z = blockIdx.z;
    const float* A = g_scores + (size_t)z * SEQ * SEQ;
    const float* V = g_v + (size_t)z * SEQ * HIDDEN;
    float* C = out + (size_t)z * SEQ * HIDDEN;

    const int tile_n = blockIdx.x * 64;
    const int tile_m = blockIdx.y * 64;
    const int t  = threadIdx.x;
    const int tx = t & 15;
    const int ty = t >> 4;

    float acc[4][4] = {};

    for (int k0 = 0; k0 < SEQ; k0 += 16) {
        #pragma unroll
        for (int i = 0; i < 4; i++) {
            int idx = t + i * 256;
            int r = idx >> 4, c = idx & 15;
            As[r][c] = A[(size_t)(tile_m + r) * SEQ + k0 + c];
        }
        #pragma unroll
        for (int i = 0; i < 4; i++) {
            int idx = t + i * 256;
            int r = idx >> 6, c = idx & 63;
            Bs[r][c] = V[(size_t)(k0 + r) * HIDDEN + tile_n + c];
        }
        __syncthreads();
        #pragma unroll
        for (int kk = 0; kk < 16; kk++) {
            float a[4], b[4];
            #pragma unroll
            for (int i = 0; i < 4; i++) a[i] = As[ty * 4 + i][kk];
            #pragma unroll
            for (int j = 0; j < 4; j++) b[j] = Bs[kk][tx * 4 + j];
            #pragma unroll
            for (int i = 0; i < 4; i++)
                #pragma unroll
                for (int j = 0; j < 4; j++)
                    acc[i][j] = fmaf(a[i], b[j], acc[i][j]);
        }
        __syncthreads();
    }

    #pragma unroll
    for (int i = 0; i < 4; i++) {
        int row = tile_m + ty * 4 + i;
        #pragma unroll
        for (int j = 0; j < 4; j++) {
            int col = tile_n + tx * 4 + j;
            C[(size_t)row * HIDDEN + col] = acc[i][j];
        }
    }
}

// ============================================================
// launch
// ============================================================
extern "C" void kernel_launch(void* const* d_in, const int* in_sizes, int n_in,
                              void* d_out, int out_size)
{
    const int*   tok = (const int*)  d_in[0];
    const float* emb = (const float*)d_in[1];
    const float* W1  = (const float*)d_in[2];
    const float* b1  = (const float*)d_in[3];
    const float* Wq  = (const float*)d_in[4];
    const float* bq  = (const float*)d_in[5];
    const float* Wk  = (const float*)d_in[6];
    const float* bk  = (const float*)d_in[7];
    const float* Wv  = (const float*)d_in[8];
    const float* bv  = (const float*)d_in[9];
    float* out = (float*)d_out;

    dim3 blk(256);
    embed_mlp_kernel<<<dim3(HIDDEN / 64, ROWS / 64), blk>>>(tok, emb, W1, b1);
    qkv_kernel<<<dim3(HIDDEN / 64, ROWS / 64, 3), blk>>>(Wq, bq, Wk, bk, Wv, bv);
    scores_kernel<<<dim3(SEQ / 64, SEQ / 64, BATCH), blk>>>();
    softmax_kernel<<<dim3(ROWS), blk>>>();
    out_kernel<<<dim3(HIDDEN / 64, SEQ / 64, BATCH), blk>>>(out);
}